// round 7
// baseline (speedup 1.0000x reference)
#include <cuda_runtime.h>
#include <cuda_fp16.h>
#include <cstdint>

// Problem constants
#define B_SZ 256
#define W_SZ 4096
#define L_SZ 16
#define K_SZ 8

#define NCTA 512              // persistent grid: 512 CTAs x 256 thr = 4096 warps = W
#define NLEVELS (L_SZ - 1)    // 15

// One buffer per level boundary: h[l] = activations entering level l.
// 16 * 4096 * 256 * 2B = 32 MB (L2 is ~126 MB). Within a launch each address
// is written once and only read after the grid barrier -> L1 caching is safe.
__device__ __half g_buf[L_SZ][(size_t)W_SZ * B_SZ];

// Detected element width of inv_mask input: 1 (bool/uint8) or 4 (int32/float32).
__device__ int g_inv_width;

// Grid-barrier state (reset by prior_transpose_kernel each replay).
__device__ unsigned g_ctr[NLEVELS];
__device__ unsigned g_rel[NLEVELS];

// ---------------------------------------------------------------------------
// Kernel 1: fused prior + transpose (+ parallel inv width detect + barrier reset).
//   h[0][n][b] = (half) relu(obs[b][n] * pw[n] + pb[n])
// ---------------------------------------------------------------------------
__global__ void __launch_bounds__(256) prior_transpose_kernel(
    const float* __restrict__ obs,
    const float* __restrict__ pw,
    const float* __restrict__ pb,
    const unsigned char* __restrict__ inv)
{
    if (blockIdx.x == 0 && blockIdx.y == 0) {
        const int t = threadIdx.y * 32 + threadIdx.x;          // 0..255
        const int pred = (inv[t * 4 + 1] != 0) ? 1 : 0;        // coalesced
        const int any = __syncthreads_or(pred);
        if (t == 0) g_inv_width = any ? 1 : 4;
        if (t < NLEVELS) { g_ctr[t] = 0u; g_rel[t] = 0u; }
        __threadfence();
    }

    __shared__ float tile[32][33];
    const int n0 = blockIdx.x * 32;
    const int b0 = blockIdx.y * 32;
    const int tx = threadIdx.x;   // 0..31
    const int ty = threadIdx.y;   // 0..7

#pragma unroll
    for (int j = 0; j < 4; j++) {
        int b = b0 + ty + j * 8;
        tile[ty + j * 8][tx] = obs[(size_t)b * W_SZ + n0 + tx];  // tile[b_local][n_local]
    }
    __syncthreads();
#pragma unroll
    for (int j = 0; j < 4; j++) {
        int n = n0 + ty + j * 8;
        int b = b0 + tx;
        float v = tile[tx][ty + j * 8];
        v = fmaxf(fmaf(v, __ldg(pw + n), __ldg(pb + n)), 0.0f);
        g_buf[0][(size_t)n * B_SZ + b] = __float2half_rn(v);
    }
}

// ---------------------------------------------------------------------------
// Grid barrier. All 512 CTAs co-resident (launch_bounds(256,4): 4*148=592).
// ---------------------------------------------------------------------------
__device__ __forceinline__ void grid_barrier(int l)
{
    __syncthreads();
    if (threadIdx.x == 0) {
        __threadfence();                                   // publish stores
        unsigned old = atomicAdd(&g_ctr[l], 1u);
        if (old == NCTA - 1) {
            atomicExch(&g_rel[l], 1u);
        } else {
            const volatile unsigned* rel = (const volatile unsigned*)&g_rel[l];
            long long spins = 0;
            while (*rel == 0u) {
                if (++spins > (1LL << 27)) break;          // safety valve
            }
        }
        __threadfence();                                   // acquire
    }
    __syncthreads();
}

// ---------------------------------------------------------------------------
// Kernel 2: persistent scan — all 15 levels in one launch.
//   h[l+1][n][b] = relu( Σ_k w'[n,k] * h[l][p[n,k]][b] + bias'[n] )
// One warp per n; lane owns 8 consecutive b (one 16B load) -> each gather is
// a fully coalesced 512B warp read. Next-level params are prefetched BEFORE
// the grid barrier so their latency hides behind the barrier wait.
// ---------------------------------------------------------------------------
__global__ void __launch_bounds__(256, 4) scan_kernel(
    const float*         __restrict__ weights,   // [L-1][W][K]
    const float*         __restrict__ biases,    // [L-1][W]
    const int*           __restrict__ parents,   // [L-1][W][K]
    const unsigned char* __restrict__ inv_base)  // [L-1][W]
{
    const int n    = (blockIdx.x * 256 + threadIdx.x) >> 5;  // global warp id = n
    const int b    = (threadIdx.x & 31) << 3;                // lane's 8-half slice
    const int invw = g_inv_width;

    // --- load level-0 params ---
    int4 p0, p1; float4 w0, w1; float bb; bool iv;
    {
        const int4*   pp = reinterpret_cast<const int4*>(parents + (size_t)n * K_SZ);
        const float4* wp = reinterpret_cast<const float4*>(weights + (size_t)n * K_SZ);
        p0 = __ldg(pp); p1 = __ldg(pp + 1);
        w0 = __ldg(wp); w1 = __ldg(wp + 1);
        bb = __ldg(biases + n);
        if (invw == 4) {
            const unsigned* iw = reinterpret_cast<const unsigned*>(inv_base);
            iv = (__ldg(iw + n) != 0u);
        } else {
            iv = (__ldg(inv_base + n) != 0);
        }
    }

#pragma unroll 1
    for (int l = 0; l < NLEVELS; l++) {
        const __half* __restrict__ hin  = g_buf[l];
        __half*       __restrict__ hout = g_buf[l + 1];

        // Fold inversion:  Σ w*(1-x) + b  ==  Σ (-w)*x + (b + Σw)
        float sw = ((w0.x + w0.y) + (w0.z + w0.w)) + ((w1.x + w1.y) + (w1.z + w1.w));
        float base = iv ? (bb + sw) : bb;
        float sgn  = iv ? -1.0f : 1.0f;
        float wk[K_SZ];
        wk[0] = w0.x * sgn; wk[1] = w0.y * sgn; wk[2] = w0.z * sgn; wk[3] = w0.w * sgn;
        wk[4] = w1.x * sgn; wk[5] = w1.y * sgn; wk[6] = w1.z * sgn; wk[7] = w1.w * sgn;
        int pk[K_SZ];
        pk[0] = p0.x; pk[1] = p0.y; pk[2] = p0.z; pk[3] = p0.w;
        pk[4] = p1.x; pk[5] = p1.y; pk[6] = p1.z; pk[7] = p1.w;

        float acc[8];
#pragma unroll
        for (int i = 0; i < 8; i++) acc[i] = base;

        const __half* hb = hin + b;

#pragma unroll
        for (int k = 0; k < K_SZ; k++) {
            int4 raw = __ldg(reinterpret_cast<const int4*>(hb + (((size_t)pk[k]) << 8)));
            __half2 h0 = *reinterpret_cast<__half2*>(&raw.x);
            __half2 h1 = *reinterpret_cast<__half2*>(&raw.y);
            __half2 h2 = *reinterpret_cast<__half2*>(&raw.z);
            __half2 h3 = *reinterpret_cast<__half2*>(&raw.w);
            float2 f0 = __half22float2(h0);
            float2 f1 = __half22float2(h1);
            float2 f2 = __half22float2(h2);
            float2 f3 = __half22float2(h3);
            float w = wk[k];
            acc[0] = fmaf(w, f0.x, acc[0]); acc[1] = fmaf(w, f0.y, acc[1]);
            acc[2] = fmaf(w, f1.x, acc[2]); acc[3] = fmaf(w, f1.y, acc[3]);
            acc[4] = fmaf(w, f2.x, acc[4]); acc[5] = fmaf(w, f2.y, acc[5]);
            acc[6] = fmaf(w, f3.x, acc[6]); acc[7] = fmaf(w, f3.y, acc[7]);
        }

#pragma unroll
        for (int i = 0; i < 8; i++) acc[i] = fmaxf(acc[i], 0.0f);

        __half2 o0 = __floats2half2_rn(acc[0], acc[1]);
        __half2 o1 = __floats2half2_rn(acc[2], acc[3]);
        __half2 o2 = __floats2half2_rn(acc[4], acc[5]);
        __half2 o3 = __floats2half2_rn(acc[6], acc[7]);
        int4 outv;
        outv.x = *reinterpret_cast<int*>(&o0);
        outv.y = *reinterpret_cast<int*>(&o1);
        outv.z = *reinterpret_cast<int*>(&o2);
        outv.w = *reinterpret_cast<int*>(&o3);
        *reinterpret_cast<int4*>(hout + (size_t)n * B_SZ + b) = outv;

        if (l < NLEVELS - 1) {
            // Prefetch next-level params BEFORE the barrier (hides L2 latency).
            const size_t poff = (size_t)(l + 1) * W_SZ * K_SZ + (size_t)n * K_SZ;
            const int4*   pp = reinterpret_cast<const int4*>(parents + poff);
            const float4* wp = reinterpret_cast<const float4*>(weights + poff);
            p0 = __ldg(pp); p1 = __ldg(pp + 1);
            w0 = __ldg(wp); w1 = __ldg(wp + 1);
            bb = __ldg(biases + (size_t)(l + 1) * W_SZ + n);
            if (invw == 4) {
                const unsigned* iw = reinterpret_cast<const unsigned*>(inv_base);
                iv = (__ldg(iw + (size_t)(l + 1) * W_SZ + n) != 0u);
            } else {
                iv = (__ldg(inv_base + (size_t)(l + 1) * W_SZ + n) != 0);
            }
            grid_barrier(l);
        }
    }
}

// ---------------------------------------------------------------------------
// Kernel 3: final transpose back to reference layout (half -> float).
//   out[b][n] = (float) g_buf[15][n][b]
// ---------------------------------------------------------------------------
__global__ void __launch_bounds__(256) out_transpose_kernel(float* __restrict__ out)
{
    __shared__ float tile[32][33];
    const int b0 = blockIdx.x * 32;
    const int n0 = blockIdx.y * 32;
    const int tx = threadIdx.x;
    const int ty = threadIdx.y;

#pragma unroll
    for (int j = 0; j < 4; j++) {
        int n = n0 + ty + j * 8;
        tile[ty + j * 8][tx] = __half2float(g_buf[NLEVELS][(size_t)n * B_SZ + b0 + tx]);
    }
    __syncthreads();
#pragma unroll
    for (int j = 0; j < 4; j++) {
        int b = b0 + ty + j * 8;
        out[(size_t)b * W_SZ + n0 + tx] = tile[tx][ty + j * 8];
    }
}

// ---------------------------------------------------------------------------
// Launch
// ---------------------------------------------------------------------------
extern "C" void kernel_launch(void* const* d_in, const int* in_sizes, int n_in,
                              void* d_out, int out_size)
{
    const float*         obs     = (const float*)d_in[0];         // [B, W]
    const float*         pw      = (const float*)d_in[1];         // [W]
    const float*         pb      = (const float*)d_in[2];         // [W]
    const float*         weights = (const float*)d_in[3];         // [L-1, W, K]
    const float*         biases  = (const float*)d_in[4];         // [L-1, W]
    const int*           parents = (const int*)d_in[5];           // [L-1, W, K]
    const unsigned char* inv     = (const unsigned char*)d_in[6]; // [L-1, W]
    float*               out     = (float*)d_out;                 // [B, W]

    (void)in_sizes; (void)n_in; (void)out_size;

    // Prior + transpose into g_buf[0]; resets barrier state; detects inv width.
    prior_transpose_kernel<<<dim3(W_SZ / 32, B_SZ / 32), dim3(32, 8)>>>(obs, pw, pb, inv);

    // All 15 levels in one persistent launch.
    scan_kernel<<<NCTA, 256>>>(weights, biases, parents, inv);

    // Transpose final activations (g_buf[15]) to output layout.
    out_transpose_kernel<<<dim3(B_SZ / 32, W_SZ / 32), dim3(32, 8)>>>(out);
}

// round 8
// speedup vs baseline: 1.1979x; 1.1979x over previous
#include <cuda_runtime.h>
#include <cuda_fp16.h>
#include <cstdint>

// Problem constants
#define B_SZ 256
#define W_SZ 4096
#define L_SZ 16
#define K_SZ 8

// Ping-pong activation scratch, fp16, transposed layout: h_t[n][b] (b fast).
// 2 * 4096 * 256 * 2B = 4 MB  -> fully L2-resident.
__device__ __half g_h[2][(size_t)W_SZ * B_SZ];

// Detected element width of inv_mask input: 1 (bool/uint8) or 4 (int32/float32).
__device__ int g_inv_width;

// ---------------------------------------------------------------------------
// Kernel 1: fused prior + transpose (+ PARALLEL inv width detection, block 0).
//   h_t[n][b] = (half) relu(obs[b][n] * pw[n] + pb[n])
//
// Width detection: for 4-byte encodings of {0,1} (int32 or float32), every
// byte at offset ==1 (mod 4) is zero. For 1-byte bools those bytes are
// ~Bernoulli(0.5). 256 parallel samples -> false-positive prob 2^-256.
// ---------------------------------------------------------------------------
__global__ void __launch_bounds__(256) prior_transpose_kernel(
    const float* __restrict__ obs,
    const float* __restrict__ pw,
    const float* __restrict__ pb,
    const unsigned char* __restrict__ inv)
{
    if (blockIdx.x == 0 && blockIdx.y == 0) {
        const int t = threadIdx.y * 32 + threadIdx.x;          // 0..255
        const int pred = (inv[t * 4 + 1] != 0) ? 1 : 0;        // coalesced
        const int any = __syncthreads_or(pred);
        if (t == 0) g_inv_width = any ? 1 : 4;
    }

    __shared__ float tile[32][33];
    const int n0 = blockIdx.x * 32;
    const int b0 = blockIdx.y * 32;
    const int tx = threadIdx.x;   // 0..31
    const int ty = threadIdx.y;   // 0..7

#pragma unroll
    for (int j = 0; j < 4; j++) {
        int b = b0 + ty + j * 8;
        tile[ty + j * 8][tx] = obs[(size_t)b * W_SZ + n0 + tx];  // tile[b_local][n_local]
    }
    __syncthreads();
#pragma unroll
    for (int j = 0; j < 4; j++) {
        int n = n0 + ty + j * 8;
        int b = b0 + tx;
        float v = tile[tx][ty + j * 8];
        v = fmaxf(fmaf(v, __ldg(pw + n), __ldg(pb + n)), 0.0f);
        g_h[0][(size_t)n * B_SZ + b] = __float2half_rn(v);
    }
}

// ---------------------------------------------------------------------------
// Kernel 2: one scan level, fp16 activations / fp32 math.
//   h_out[n][b] = relu( Σ_k w'[n,k] * h_in[p[n,k]][b] + bias'[n] )
// 64 threads per n (2 warps, both n-uniform -> params are single
// transactions). Each lane owns 4 consecutive b as one 8B load -> each
// gather is a fully coalesced 256B warp read.
// Grid: W*64 threads = 262144 -> 1024 blocks of 256; launch_bounds(256,8)
// caps regs at 32 -> 8 CTAs/SM -> all 1024 CTAs co-resident in one wave.
// ---------------------------------------------------------------------------
__global__ void __launch_bounds__(256, 8) level_kernel(
    int src,
    int lvl,
    const float*         __restrict__ weights,   // [W][K] for this level
    const float*         __restrict__ biases,    // [W]
    const int*           __restrict__ parents,   // [W][K]
    const unsigned char* __restrict__ inv_base)  // [L-1][W]
{
    const __half* __restrict__ hin  = g_h[src];
    __half*       __restrict__ hout = g_h[src ^ 1];

    const int gid = blockIdx.x * 256 + threadIdx.x;
    const int n   = gid >> 6;          // 64 threads per n
    const int b   = (gid & 63) << 2;   // lane's 4-half batch slice

    // Per-n params (uniform across each warp's lanes -> single transactions)
    const int4*   pp = reinterpret_cast<const int4*>(parents + (size_t)n * K_SZ);
    const float4* wp = reinterpret_cast<const float4*>(weights + (size_t)n * K_SZ);
    int4   p0 = __ldg(pp);
    int4   p1 = __ldg(pp + 1);
    float4 w0 = __ldg(wp);
    float4 w1 = __ldg(wp + 1);
    float  bb = __ldg(biases + n);

    bool iv;
    if (g_inv_width == 4) {
        const unsigned* iw = reinterpret_cast<const unsigned*>(inv_base);
        iv = (__ldg(iw + (size_t)lvl * W_SZ + n) != 0u);
    } else {
        iv = (__ldg(inv_base + (size_t)lvl * W_SZ + n) != 0);
    }

    // Fold inversion:  Σ w*(1-x) + b  ==  Σ (-w)*x + (b + Σw)
    float sw = ((w0.x + w0.y) + (w0.z + w0.w)) + ((w1.x + w1.y) + (w1.z + w1.w));
    float base = iv ? (bb + sw) : bb;
    float sgn  = iv ? -1.0f : 1.0f;
    float wk[K_SZ];
    wk[0] = w0.x * sgn; wk[1] = w0.y * sgn; wk[2] = w0.z * sgn; wk[3] = w0.w * sgn;
    wk[4] = w1.x * sgn; wk[5] = w1.y * sgn; wk[6] = w1.z * sgn; wk[7] = w1.w * sgn;
    int pk[K_SZ];
    pk[0] = p0.x; pk[1] = p0.y; pk[2] = p0.z; pk[3] = p0.w;
    pk[4] = p1.x; pk[5] = p1.y; pk[6] = p1.z; pk[7] = p1.w;

    float acc[4];
#pragma unroll
    for (int i = 0; i < 4; i++) acc[i] = base;

    const __half* hb = hin + b;

#pragma unroll
    for (int k = 0; k < K_SZ; k++) {
        // 8B gather: 4 halves of this n's parent row
        int2 raw = __ldg(reinterpret_cast<const int2*>(hb + (((size_t)pk[k]) << 8)));
        __half2 h0 = *reinterpret_cast<__half2*>(&raw.x);
        __half2 h1 = *reinterpret_cast<__half2*>(&raw.y);
        float2 f0 = __half22float2(h0);
        float2 f1 = __half22float2(h1);
        float w = wk[k];
        acc[0] = fmaf(w, f0.x, acc[0]); acc[1] = fmaf(w, f0.y, acc[1]);
        acc[2] = fmaf(w, f1.x, acc[2]); acc[3] = fmaf(w, f1.y, acc[3]);
    }

#pragma unroll
    for (int i = 0; i < 4; i++) acc[i] = fmaxf(acc[i], 0.0f);

    __half2 o0 = __floats2half2_rn(acc[0], acc[1]);
    __half2 o1 = __floats2half2_rn(acc[2], acc[3]);
    int2 outv;
    outv.x = *reinterpret_cast<int*>(&o0);
    outv.y = *reinterpret_cast<int*>(&o1);
    *reinterpret_cast<int2*>(hout + (size_t)n * B_SZ + b) = outv;
}

// ---------------------------------------------------------------------------
// Kernel 3: final transpose back to reference layout (half -> float).
//   out[b][n] = (float) h_t[n][b]   (source buffer index 1 after 15 levels)
// ---------------------------------------------------------------------------
__global__ void __launch_bounds__(256) out_transpose_kernel(float* __restrict__ out)
{
    __shared__ float tile[32][33];
    const int b0 = blockIdx.x * 32;
    const int n0 = blockIdx.y * 32;
    const int tx = threadIdx.x;
    const int ty = threadIdx.y;

#pragma unroll
    for (int j = 0; j < 4; j++) {
        int n = n0 + ty + j * 8;
        tile[ty + j * 8][tx] = __half2float(g_h[1][(size_t)n * B_SZ + b0 + tx]);
    }
    __syncthreads();
#pragma unroll
    for (int j = 0; j < 4; j++) {
        int b = b0 + ty + j * 8;
        out[(size_t)b * W_SZ + n0 + tx] = tile[tx][ty + j * 8];
    }
}

// ---------------------------------------------------------------------------
// Launch
// ---------------------------------------------------------------------------
extern "C" void kernel_launch(void* const* d_in, const int* in_sizes, int n_in,
                              void* d_out, int out_size)
{
    const float*         obs     = (const float*)d_in[0];         // [B, W]
    const float*         pw      = (const float*)d_in[1];         // [W]
    const float*         pb      = (const float*)d_in[2];         // [W]
    const float*         weights = (const float*)d_in[3];         // [L-1, W, K]
    const float*         biases  = (const float*)d_in[4];         // [L-1, W]
    const int*           parents = (const int*)d_in[5];           // [L-1, W, K]
    const unsigned char* inv     = (const unsigned char*)d_in[6]; // [L-1, W]
    float*               out     = (float*)d_out;                 // [B, W]

    (void)in_sizes; (void)n_in; (void)out_size;

    // Prior + transpose into g_h[0] (also detects inv_mask element width)
    prior_transpose_kernel<<<dim3(W_SZ / 32, B_SZ / 32), dim3(32, 8)>>>(obs, pw, pb, inv);

    // 15 scan levels, ping-pong g_h[0] <-> g_h[1]
    const int blocks = (W_SZ * 64) / 256;  // 1024
    for (int l = 0; l < L_SZ - 1; l++) {
        level_kernel<<<blocks, 256>>>(
            l & 1, l,
            weights + (size_t)l * W_SZ * K_SZ,
            biases  + (size_t)l * W_SZ,
            parents + (size_t)l * W_SZ * K_SZ,
            inv);
    }

    // After 15 levels (last l=14, even -> wrote g_h[1]), transpose to output
    out_transpose_kernel<<<dim3(B_SZ / 32, W_SZ / 32), dim3(32, 8)>>>(out);
}

// round 9
// speedup vs baseline: 1.3967x; 1.1659x over previous
#include <cuda_runtime.h>
#include <cuda_fp16.h>
#include <cstdint>

// Problem constants
#define B_SZ 256
#define W_SZ 4096
#define L_SZ 16
#define K_SZ 8

// Ping-pong activation scratch, fp16, transposed layout: h_t[n][b] (b fast).
// 2 * 4096 * 256 * 2B = 4 MB  -> fully L2-resident.
__device__ __half g_h[2][(size_t)W_SZ * B_SZ];

// Detected element width of inv_mask input: 1 (bool/uint8) or 4 (int32/float32).
__device__ int g_inv_width;

// ---------------------------------------------------------------------------
// Kernel 1: fused prior + transpose (+ PARALLEL inv width detection, block 0).
//   h_t[n][b] = (half) relu(obs[b][n] * pw[n] + pb[n])
// ---------------------------------------------------------------------------
__global__ void __launch_bounds__(256) prior_transpose_kernel(
    const float* __restrict__ obs,
    const float* __restrict__ pw,
    const float* __restrict__ pb,
    const unsigned char* __restrict__ inv)
{
    if (blockIdx.x == 0 && blockIdx.y == 0) {
        const int t = threadIdx.y * 32 + threadIdx.x;          // 0..255
        const int pred = (inv[t * 4 + 1] != 0) ? 1 : 0;        // coalesced
        const int any = __syncthreads_or(pred);
        if (t == 0) g_inv_width = any ? 1 : 4;
    }

    __shared__ float tile[32][33];
    const int n0 = blockIdx.x * 32;
    const int b0 = blockIdx.y * 32;
    const int tx = threadIdx.x;   // 0..31
    const int ty = threadIdx.y;   // 0..7

#pragma unroll
    for (int j = 0; j < 4; j++) {
        int b = b0 + ty + j * 8;
        tile[ty + j * 8][tx] = obs[(size_t)b * W_SZ + n0 + tx];  // tile[b_local][n_local]
    }
    __syncthreads();
#pragma unroll
    for (int j = 0; j < 4; j++) {
        int n = n0 + ty + j * 8;
        int b = b0 + tx;
        float v = tile[tx][ty + j * 8];
        v = fmaxf(fmaf(v, __ldg(pw + n), __ldg(pb + n)), 0.0f);
        g_h[0][(size_t)n * B_SZ + b] = __float2half_rn(v);
    }
#if __CUDA_ARCH__ >= 900
    cudaTriggerProgrammaticLaunchCompletion();
#endif
}

// ---------------------------------------------------------------------------
// Kernel 2: one scan level with PDL overlap.
//   Prologue (param loads — pure inputs) runs while the PREVIOUS level is
//   still draining; cudaGridDependencySynchronize() acquires its output;
//   gathers issue immediately after.
//   h_out[n][b] = relu( b' +/- Σ_k w[n,k] * h_in[p[n,k]][b] )
// One warp per n; lane owns 8 consecutive b (one 16B load) -> each gather
// is a fully coalesced 512B warp read.
// ---------------------------------------------------------------------------
__global__ void __launch_bounds__(256) level_kernel(
    int src,
    int lvl,
    const float*         __restrict__ weights,   // [W][K] for this level
    const float*         __restrict__ biases,    // [W]
    const int*           __restrict__ parents,   // [W][K]
    const unsigned char* __restrict__ inv_base)  // [L-1][W]
{
    const int gid = blockIdx.x * 256 + threadIdx.x;
    const int n   = gid >> 5;          // 32 threads per n
    const int b   = (gid & 31) << 3;   // lane's 8-wide batch slice

    // ---- PDL prologue: input-only loads (overlap predecessor tail) ----
    const int4*   pp = reinterpret_cast<const int4*>(parents + (size_t)n * K_SZ);
    const float4* wp = reinterpret_cast<const float4*>(weights + (size_t)n * K_SZ);
    int4   p0 = __ldg(pp);
    int4   p1 = __ldg(pp + 1);
    float4 w0 = __ldg(wp);
    float4 w1 = __ldg(wp + 1);
    float  bb = __ldg(biases + n);
    float  sw = ((w0.x + w0.y) + (w0.z + w0.w)) + ((w1.x + w1.y) + (w1.z + w1.w));
    float  base_inv = bb + sw;

    float wk[K_SZ];
    wk[0] = w0.x; wk[1] = w0.y; wk[2] = w0.z; wk[3] = w0.w;
    wk[4] = w1.x; wk[5] = w1.y; wk[6] = w1.z; wk[7] = w1.w;
    int pk[K_SZ];
    pk[0] = p0.x; pk[1] = p0.y; pk[2] = p0.z; pk[3] = p0.w;
    pk[4] = p1.x; pk[5] = p1.y; pk[6] = p1.z; pk[7] = p1.w;

#if __CUDA_ARCH__ >= 900
    cudaGridDependencySynchronize();   // previous level's stores now visible
#endif

    const __half* __restrict__ hin  = g_h[src];
    __half*       __restrict__ hout = g_h[src ^ 1];
    const __half* hb = hin + b;

    float acc[8];
#pragma unroll
    for (int i = 0; i < 8; i++) acc[i] = 0.0f;

#pragma unroll
    for (int k = 0; k < K_SZ; k++) {
        int4 raw = __ldg(reinterpret_cast<const int4*>(hb + (((size_t)pk[k]) << 8)));
        __half2 h0 = *reinterpret_cast<__half2*>(&raw.x);
        __half2 h1 = *reinterpret_cast<__half2*>(&raw.y);
        __half2 h2 = *reinterpret_cast<__half2*>(&raw.z);
        __half2 h3 = *reinterpret_cast<__half2*>(&raw.w);
        float2 f0 = __half22float2(h0);
        float2 f1 = __half22float2(h1);
        float2 f2 = __half22float2(h2);
        float2 f3 = __half22float2(h3);
        float w = wk[k];
        acc[0] = fmaf(w, f0.x, acc[0]); acc[1] = fmaf(w, f0.y, acc[1]);
        acc[2] = fmaf(w, f1.x, acc[2]); acc[3] = fmaf(w, f1.y, acc[3]);
        acc[4] = fmaf(w, f2.x, acc[4]); acc[5] = fmaf(w, f2.y, acc[5]);
        acc[6] = fmaf(w, f3.x, acc[6]); acc[7] = fmaf(w, f3.y, acc[7]);
    }

    // inv resolution (post-sync: g_inv_width written by prior kernel);
    // the 2-deep load chain hides under the in-flight gathers above.
    bool iv;
    if (g_inv_width == 4) {
        const unsigned* iw = reinterpret_cast<const unsigned*>(inv_base);
        iv = (__ldg(iw + (size_t)lvl * W_SZ + n) != 0u);
    } else {
        iv = (__ldg(inv_base + (size_t)lvl * W_SZ + n) != 0);
    }
    //  Σ w*(1-x) + b == (b + Σw) - Σ w*x
    float basev = iv ? base_inv : bb;
    float sgn   = iv ? -1.0f : 1.0f;

#pragma unroll
    for (int i = 0; i < 8; i++) acc[i] = fmaxf(fmaf(sgn, acc[i], basev), 0.0f);

    __half2 o0 = __floats2half2_rn(acc[0], acc[1]);
    __half2 o1 = __floats2half2_rn(acc[2], acc[3]);
    __half2 o2 = __floats2half2_rn(acc[4], acc[5]);
    __half2 o3 = __floats2half2_rn(acc[6], acc[7]);
    int4 outv;
    outv.x = *reinterpret_cast<int*>(&o0);
    outv.y = *reinterpret_cast<int*>(&o1);
    outv.z = *reinterpret_cast<int*>(&o2);
    outv.w = *reinterpret_cast<int*>(&o3);
    *reinterpret_cast<int4*>(hout + (size_t)n * B_SZ + b) = outv;

#if __CUDA_ARCH__ >= 900
    cudaTriggerProgrammaticLaunchCompletion();   // hand off to next level early
#endif
}

// ---------------------------------------------------------------------------
// Kernel 3: final transpose back to reference layout (half -> float).
//   out[b][n] = (float) h_t[n][b]   (source buffer index 1 after 15 levels)
// ---------------------------------------------------------------------------
__global__ void __launch_bounds__(256) out_transpose_kernel(float* __restrict__ out)
{
#if __CUDA_ARCH__ >= 900
    cudaGridDependencySynchronize();
#endif
    __shared__ float tile[32][33];
    const int b0 = blockIdx.x * 32;
    const int n0 = blockIdx.y * 32;
    const int tx = threadIdx.x;
    const int ty = threadIdx.y;

#pragma unroll
    for (int j = 0; j < 4; j++) {
        int n = n0 + ty + j * 8;
        tile[ty + j * 8][tx] = __half2float(g_h[1][(size_t)n * B_SZ + b0 + tx]);
    }
    __syncthreads();
#pragma unroll
    for (int j = 0; j < 4; j++) {
        int b = b0 + ty + j * 8;
        out[(size_t)b * W_SZ + n0 + tx] = tile[tx][ty + j * 8];
    }
}

// ---------------------------------------------------------------------------
// Launch: levels + out-transpose launched with the PDL (programmatic stream
// serialization) attribute so each kernel's prologue overlaps its
// predecessor's tail. Falls back to correct serial semantics if the attr
// is ignored (the grid-sync still acquires predecessor completion).
// ---------------------------------------------------------------------------
extern "C" void kernel_launch(void* const* d_in, const int* in_sizes, int n_in,
                              void* d_out, int out_size)
{
    const float*         obs     = (const float*)d_in[0];         // [B, W]
    const float*         pw      = (const float*)d_in[1];         // [W]
    const float*         pb      = (const float*)d_in[2];         // [W]
    const float*         weights = (const float*)d_in[3];         // [L-1, W, K]
    const float*         biases  = (const float*)d_in[4];         // [L-1, W]
    const int*           parents = (const int*)d_in[5];           // [L-1, W, K]
    const unsigned char* inv     = (const unsigned char*)d_in[6]; // [L-1, W]
    float*               out     = (float*)d_out;                 // [B, W]

    (void)in_sizes; (void)n_in; (void)out_size;

    // Prior + transpose into g_h[0] (also detects inv_mask element width)
    prior_transpose_kernel<<<dim3(W_SZ / 32, B_SZ / 32), dim3(32, 8)>>>(obs, pw, pb, inv);

    cudaLaunchAttribute attrs[1];
    attrs[0].id = cudaLaunchAttributeProgrammaticStreamSerialization;
    attrs[0].val.programmaticStreamSerializationAllowed = 1;

    // 15 scan levels, ping-pong g_h[0] <-> g_h[1], PDL-chained
    const int blocks = (W_SZ * 32) / 256;  // 512
    for (int l = 0; l < L_SZ - 1; l++) {
        cudaLaunchConfig_t cfg = {};
        cfg.gridDim  = dim3(blocks, 1, 1);
        cfg.blockDim = dim3(256, 1, 1);
        cfg.dynamicSmemBytes = 0;
        cfg.stream = 0;
        cfg.attrs = attrs;
        cfg.numAttrs = 1;
        cudaLaunchKernelEx(&cfg, level_kernel,
            l & 1, l,
            (const float*)(weights + (size_t)l * W_SZ * K_SZ),
            (const float*)(biases  + (size_t)l * W_SZ),
            (const int*)(parents + (size_t)l * W_SZ * K_SZ),
            (const unsigned char*)inv);
    }

    // Transpose final activations (g_h[1]) to output layout, PDL-chained.
    {
        cudaLaunchConfig_t cfg = {};
        cfg.gridDim  = dim3(B_SZ / 32, W_SZ / 32, 1);
        cfg.blockDim = dim3(32, 8, 1);
        cfg.dynamicSmemBytes = 0;
        cfg.stream = 0;
        cfg.attrs = attrs;
        cfg.numAttrs = 1;
        cudaLaunchKernelEx(&cfg, out_transpose_kernel, out);
    }
}

// round 10
// speedup vs baseline: 1.5364x; 1.1001x over previous
#include <cuda_runtime.h>
#include <cuda_fp16.h>
#include <cstdint>

// Problem constants
#define B_SZ 256
#define W_SZ 4096
#define L_SZ 16
#define K_SZ 8

// Ping-pong activation scratch, fp16, transposed layout: h_t[n][b] (b fast).
// 2 * 4096 * 256 * 2B = 4 MB  -> fully L2-resident.
__device__ __half g_h[2][(size_t)W_SZ * B_SZ];

// Detected element width of inv_mask input: 1 (bool/uint8) or 4 (int32/float32).
__device__ int g_inv_width;

// ---------------------------------------------------------------------------
// Kernel 1: fused prior + transpose (+ PARALLEL inv width detection, block 0).
//   h_t[n][b] = (half) relu(obs[b][n] * pw[n] + pb[n])
// ---------------------------------------------------------------------------
__global__ void __launch_bounds__(256) prior_transpose_kernel(
    const float* __restrict__ obs,
    const float* __restrict__ pw,
    const float* __restrict__ pb,
    const unsigned char* __restrict__ inv)
{
    if (blockIdx.x == 0 && blockIdx.y == 0) {
        const int t = threadIdx.y * 32 + threadIdx.x;          // 0..255
        const int pred = (inv[t * 4 + 1] != 0) ? 1 : 0;        // coalesced
        const int any = __syncthreads_or(pred);
        if (t == 0) g_inv_width = any ? 1 : 4;
    }

    __shared__ float tile[32][33];
    const int n0 = blockIdx.x * 32;
    const int b0 = blockIdx.y * 32;
    const int tx = threadIdx.x;   // 0..31
    const int ty = threadIdx.y;   // 0..7

#pragma unroll
    for (int j = 0; j < 4; j++) {
        int b = b0 + ty + j * 8;
        tile[ty + j * 8][tx] = obs[(size_t)b * W_SZ + n0 + tx];  // tile[b_local][n_local]
    }
    __syncthreads();
#pragma unroll
    for (int j = 0; j < 4; j++) {
        int n = n0 + ty + j * 8;
        int b = b0 + tx;
        float v = tile[tx][ty + j * 8];
        v = fmaxf(fmaf(v, __ldg(pw + n), __ldg(pb + n)), 0.0f);
        g_h[0][(size_t)n * B_SZ + b] = __float2half_rn(v);
    }
#if __CUDA_ARCH__ >= 900
    cudaTriggerProgrammaticLaunchCompletion();
#endif
}

// ---------------------------------------------------------------------------
// Kernel 2: one scan level with PDL overlap and full-depth gather batch.
//   Prologue (params + all 8 gather ADDRESSES — input-only) overlaps the
//   previous level's tail; after cudaGridDependencySynchronize() all 8
//   LDG.128 gathers issue back-to-back (MLP=8), then convert+FMA.
//   h_out[n][b] = relu( b' +/- Σ_k w[n,k] * h_in[p[n,k]][b] )
// ---------------------------------------------------------------------------
__global__ void __launch_bounds__(256, 4) level_kernel(
    int src,
    int lvl,
    const float*         __restrict__ weights,   // [W][K] for this level
    const float*         __restrict__ biases,    // [W]
    const int*           __restrict__ parents,   // [W][K]
    const unsigned char* __restrict__ inv_base)  // [L-1][W]
{
    const int gid = blockIdx.x * 256 + threadIdx.x;
    const int n   = gid >> 5;          // 32 threads per n
    const int b   = (gid & 31) << 3;   // lane's 8-wide batch slice

    // ---- PDL prologue: input-only loads + address math ----
    const int4*   pp = reinterpret_cast<const int4*>(parents + (size_t)n * K_SZ);
    const float4* wp = reinterpret_cast<const float4*>(weights + (size_t)n * K_SZ);
    int4   p0 = __ldg(pp);
    int4   p1 = __ldg(pp + 1);
    float4 w0 = __ldg(wp);
    float4 w1 = __ldg(wp + 1);
    float  bb = __ldg(biases + n);
    float  sw = ((w0.x + w0.y) + (w0.z + w0.w)) + ((w1.x + w1.y) + (w1.z + w1.w));
    float  base_inv = bb + sw;

    const __half* hb = g_h[src] + b;
    const int4* a0 = reinterpret_cast<const int4*>(hb + (((size_t)p0.x) << 8));
    const int4* a1 = reinterpret_cast<const int4*>(hb + (((size_t)p0.y) << 8));
    const int4* a2 = reinterpret_cast<const int4*>(hb + (((size_t)p0.z) << 8));
    const int4* a3 = reinterpret_cast<const int4*>(hb + (((size_t)p0.w) << 8));
    const int4* a4 = reinterpret_cast<const int4*>(hb + (((size_t)p1.x) << 8));
    const int4* a5 = reinterpret_cast<const int4*>(hb + (((size_t)p1.y) << 8));
    const int4* a6 = reinterpret_cast<const int4*>(hb + (((size_t)p1.z) << 8));
    const int4* a7 = reinterpret_cast<const int4*>(hb + (((size_t)p1.w) << 8));

#if __CUDA_ARCH__ >= 900
    cudaGridDependencySynchronize();   // previous level's stores now visible
#endif

    // ---- all 8 gathers in flight before any consumption (MLP = 8) ----
    int4 r0 = __ldg(a0);
    int4 r1 = __ldg(a1);
    int4 r2 = __ldg(a2);
    int4 r3 = __ldg(a3);
    int4 r4 = __ldg(a4);
    int4 r5 = __ldg(a5);
    int4 r6 = __ldg(a6);
    int4 r7 = __ldg(a7);

    float acc[8];
#pragma unroll
    for (int i = 0; i < 8; i++) acc[i] = 0.0f;

#define ACCUM(RAW, WV)                                                         \
    {                                                                          \
        float2 f0 = __half22float2(*reinterpret_cast<__half2*>(&(RAW).x));     \
        float2 f1 = __half22float2(*reinterpret_cast<__half2*>(&(RAW).y));     \
        float2 f2 = __half22float2(*reinterpret_cast<__half2*>(&(RAW).z));     \
        float2 f3 = __half22float2(*reinterpret_cast<__half2*>(&(RAW).w));     \
        acc[0] = fmaf((WV), f0.x, acc[0]); acc[1] = fmaf((WV), f0.y, acc[1]);  \
        acc[2] = fmaf((WV), f1.x, acc[2]); acc[3] = fmaf((WV), f1.y, acc[3]);  \
        acc[4] = fmaf((WV), f2.x, acc[4]); acc[5] = fmaf((WV), f2.y, acc[5]);  \
        acc[6] = fmaf((WV), f3.x, acc[6]); acc[7] = fmaf((WV), f3.y, acc[7]);  \
    }

    ACCUM(r0, w0.x)
    ACCUM(r1, w0.y)
    ACCUM(r2, w0.z)
    ACCUM(r3, w0.w)
    ACCUM(r4, w1.x)
    ACCUM(r5, w1.y)
    ACCUM(r6, w1.z)
    ACCUM(r7, w1.w)
#undef ACCUM

    // inv resolution (post-sync: g_inv_width written by the prior kernel);
    // this short load chain hides under the gathers above.
    bool iv;
    if (g_inv_width == 4) {
        const unsigned* iw = reinterpret_cast<const unsigned*>(inv_base);
        iv = (__ldg(iw + (size_t)lvl * W_SZ + n) != 0u);
    } else {
        iv = (__ldg(inv_base + (size_t)lvl * W_SZ + n) != 0);
    }
    //  Σ w*(1-x) + b == (b + Σw) - Σ w*x
    float basev = iv ? base_inv : bb;
    float sgn   = iv ? -1.0f : 1.0f;

#pragma unroll
    for (int i = 0; i < 8; i++) acc[i] = fmaxf(fmaf(sgn, acc[i], basev), 0.0f);

    __half2 o0 = __floats2half2_rn(acc[0], acc[1]);
    __half2 o1 = __floats2half2_rn(acc[2], acc[3]);
    __half2 o2 = __floats2half2_rn(acc[4], acc[5]);
    __half2 o3 = __floats2half2_rn(acc[6], acc[7]);
    int4 outv;
    outv.x = *reinterpret_cast<int*>(&o0);
    outv.y = *reinterpret_cast<int*>(&o1);
    outv.z = *reinterpret_cast<int*>(&o2);
    outv.w = *reinterpret_cast<int*>(&o3);
    *reinterpret_cast<int4*>(g_h[src ^ 1] + (size_t)n * B_SZ + b) = outv;

#if __CUDA_ARCH__ >= 900
    cudaTriggerProgrammaticLaunchCompletion();   // hand off to next level early
#endif
}

// ---------------------------------------------------------------------------
// Kernel 3: final transpose back to reference layout (half -> float).
//   out[b][n] = (float) h_t[n][b]   (source buffer index 1 after 15 levels)
// ---------------------------------------------------------------------------
__global__ void __launch_bounds__(256) out_transpose_kernel(float* __restrict__ out)
{
#if __CUDA_ARCH__ >= 900
    cudaGridDependencySynchronize();
#endif
    __shared__ float tile[32][33];
    const int b0 = blockIdx.x * 32;
    const int n0 = blockIdx.y * 32;
    const int tx = threadIdx.x;
    const int ty = threadIdx.y;

#pragma unroll
    for (int j = 0; j < 4; j++) {
        int n = n0 + ty + j * 8;
        tile[ty + j * 8][tx] = __half2float(g_h[1][(size_t)n * B_SZ + b0 + tx]);
    }
    __syncthreads();
#pragma unroll
    for (int j = 0; j < 4; j++) {
        int b = b0 + ty + j * 8;
        out[(size_t)b * W_SZ + n0 + tx] = tile[tx][ty + j * 8];
    }
}

// ---------------------------------------------------------------------------
// Launch: levels + out-transpose PDL-chained (programmatic stream
// serialization), so each kernel's prologue overlaps its predecessor's tail.
// ---------------------------------------------------------------------------
extern "C" void kernel_launch(void* const* d_in, const int* in_sizes, int n_in,
                              void* d_out, int out_size)
{
    const float*         obs     = (const float*)d_in[0];         // [B, W]
    const float*         pw      = (const float*)d_in[1];         // [W]
    const float*         pb      = (const float*)d_in[2];         // [W]
    const float*         weights = (const float*)d_in[3];         // [L-1, W, K]
    const float*         biases  = (const float*)d_in[4];         // [L-1, W]
    const int*           parents = (const int*)d_in[5];           // [L-1, W, K]
    const unsigned char* inv     = (const unsigned char*)d_in[6]; // [L-1, W]
    float*               out     = (float*)d_out;                 // [B, W]

    (void)in_sizes; (void)n_in; (void)out_size;

    // Prior + transpose into g_h[0] (also detects inv_mask element width)
    prior_transpose_kernel<<<dim3(W_SZ / 32, B_SZ / 32), dim3(32, 8)>>>(obs, pw, pb, inv);

    cudaLaunchAttribute attrs[1];
    attrs[0].id = cudaLaunchAttributeProgrammaticStreamSerialization;
    attrs[0].val.programmaticStreamSerializationAllowed = 1;

    // 15 scan levels, ping-pong g_h[0] <-> g_h[1], PDL-chained
    const int blocks = (W_SZ * 32) / 256;  // 512
    for (int l = 0; l < L_SZ - 1; l++) {
        cudaLaunchConfig_t cfg = {};
        cfg.gridDim  = dim3(blocks, 1, 1);
        cfg.blockDim = dim3(256, 1, 1);
        cfg.dynamicSmemBytes = 0;
        cfg.stream = 0;
        cfg.attrs = attrs;
        cfg.numAttrs = 1;
        cudaLaunchKernelEx(&cfg, level_kernel,
            l & 1, l,
            (const float*)(weights + (size_t)l * W_SZ * K_SZ),
            (const float*)(biases  + (size_t)l * W_SZ),
            (const int*)(parents + (size_t)l * W_SZ * K_SZ),
            (const unsigned char*)inv);
    }

    // Transpose final activations (g_h[1]) to output layout, PDL-chained.
    {
        cudaLaunchConfig_t cfg = {};
        cfg.gridDim  = dim3(B_SZ / 32, W_SZ / 32, 1);
        cfg.blockDim = dim3(32, 8, 1);
        cfg.dynamicSmemBytes = 0;
        cfg.stream = 0;
        cfg.attrs = attrs;
        cfg.numAttrs = 1;
        cudaLaunchKernelEx(&cfg, out_transpose_kernel, out);
    }
}